// round 14
// baseline (speedup 1.0000x reference)
#include <cuda_runtime.h>
#include <cuda_bf16.h>
#include <math.h>
#include <stdint.h>

static constexpr int BKTOT = 16384;
static constexpr int RR    = 114688;

// ---------------- device-global scratch (allocation-free), fp32 tf32-prerounded ----
__device__ __align__(16) float g_sp [16384*256];
__device__ __align__(16) float g_xp [16384*576];
__device__ __align__(16) float g_s1 [16384*256];
__device__ __align__(16) float g_uv [16384*512];
__device__ __align__(16) float g_co [114688*256];
__device__ __align__(16) float g_cx [114688*256];
__device__ __align__(16) float g_att[114688];
__device__ __align__(16) float g_ef [16384*256];
__device__ __align__(16) float g_eW [256*256];
__device__ __align__(16) float g_uvW[512*256];
__device__ __align__(16) float g_xW [256*256];
__device__ __align__(16) float g_aW [128*256];
__device__ __align__(16) float g_oW [256*1088];

// ---------------- helpers ----------------
__device__ __forceinline__ uint32_t smem_u32(const void* p) {
    uint32_t a;
    asm("{ .reg .u64 t; cvta.to.shared.u64 t, %1; cvt.u32.u64 %0, t; }" : "=r"(a) : "l"(p));
    return a;
}
__device__ __forceinline__ void cpa16(uint32_t saddr, const void* g) {
    asm volatile("cp.async.cg.shared.global [%0], [%1], 16;" :: "r"(saddr), "l"(g));
}
#define CP_COMMIT() asm volatile("cp.async.commit_group;" ::: "memory")
#define CP_WAIT(n)  asm volatile("cp.async.wait_group %0;" :: "n"(n) : "memory")

__device__ __forceinline__ float tf32r(float x) {
    uint32_t r;
    asm("cvt.rna.tf32.f32 %0, %1;" : "=r"(r) : "f"(x));
    return __uint_as_float(r);
}
__device__ __forceinline__ void mma_tf32(float* d, const uint32_t* a, const uint32_t* b) {
    asm volatile(
        "mma.sync.aligned.m16n8k8.row.col.f32.tf32.tf32.f32 "
        "{%0,%1,%2,%3}, {%4,%5,%6,%7}, {%8,%9}, {%0,%1,%2,%3};"
        : "+f"(d[0]), "+f"(d[1]), "+f"(d[2]), "+f"(d[3])
        : "r"(a[0]), "r"(a[1]), "r"(a[2]), "r"(a[3]), "r"(b[0]), "r"(b[1]));
}
__device__ __forceinline__ float ftanh(float x) {
    float t = fminf(fmaxf(2.f * x, -30.f), 30.f);
    float e = __expf(t);
    return (e - 1.f) / (e + 1.f);
}
__device__ __forceinline__ float fsigmoid(float z) { return 1.f / (1.f + __expf(-z)); }

// ---------------- prep kernels ----------------
__global__ void cvt_pad(float* __restrict__ dst, int DS,
                        const float* __restrict__ src, int SC, int rows)
{
    int idx = blockIdx.x * blockDim.x + threadIdx.x;
    if (idx >= rows * DS) return;
    int r = idx / DS, c = idx - r * DS;
    float v = (c < SC) ? src[(size_t)r * SC + c] : 0.f;
    dst[idx] = tf32r(v);
}

struct PrepJob {
    float* dst;
    const float* W;
    int Kp, N0;
    int b0, v0, b1, v1, b2, v2;
    int count;
};
struct PrepJobs { PrepJob j[6]; int cum[7]; };

__global__ void prep_all(PrepJobs J)
{
    int e = blockIdx.x * blockDim.x + threadIdx.x;
    if (e >= J.cum[6]) return;
    int ji = 0;
    while (e >= J.cum[ji + 1]) ji++;
    const PrepJob& p = J.j[ji];
    int idx = e - J.cum[ji];
    int n = idx / p.Kp, k = idx - n * p.Kp;
    int piece = (k >= 512) ? 2 : (k >= 256) ? 1 : 0;
    int off = k - ((piece == 2) ? 512 : piece * 256);
    int base  = (piece == 0) ? p.b0 : (piece == 1) ? p.b1 : p.b2;
    int valid = (piece == 0) ? p.v0 : (piece == 1) ? p.v1 : p.v2;
    float v = (off < valid && n < p.N0) ? p.W[(size_t)(base + off) * p.N0 + n] : 0.f;
    p.dst[idx] = tf32r(v);
}

// ---------------- TF32 fused GEMM (2-stage double buffer, BK=32) ----------------
// NT threads (NT/32 warps, warp tile 32x64). GATHER: 0 plain; 2 [s1|eff|x]
// EPI: 0 bias?+fp32 store; 1 relu+LN -> tf32 plane; 2 tanh+LN+dot(W2)+sigmoid -> scalar
template<int BM, int BN, int NT, int KTOT, int GATHER, int EPI>
__global__ void __launch_bounds__(NT) tgemm(
    const float* __restrict__ A1, const float* __restrict__ A2, const float* __restrict__ A3,
    const float* __restrict__ Bw,
    const float* __restrict__ bias, const float* __restrict__ gamma, const float* __restrict__ beta,
    const float* __restrict__ W2, const float* __restrict__ b2,
    float* __restrict__ Cf, float* __restrict__ Cpl,
    int N, int astride, int bstride, int cstride)
{
    constexpr int PADF  = 36;
    constexpr int NWARP = NT / 32;
    constexpr int NWM   = BM / 32;
    constexpr int NWN   = NWARP / NWM;
    constexpr int NI    = BN / (8 * NWN);
    constexpr int NST   = KTOT / 32;
    static_assert(NWM * NWN == NWARP, "warp map");

    extern __shared__ __align__(16) float sm[];
    float* const Asm = sm;
    float* const Bsm = sm + 2 * BM * PADF;
    float* const red0 = sm + 2 * (BM + BN) * PADF;
    float* const red1 = red0 + BM * NWN;
    const uint32_t smb = smem_u32(sm);

    const int tid = threadIdx.x, w = tid >> 5, lane = tid & 31;
    const int g = lane >> 2, tq = lane & 3;
    const int wm = w % NWM, wn = w / NWM;
    const int row0 = blockIdx.x * BM;
    const int col0 = blockIdx.y * BN;
    Bw += (size_t)col0 * bstride;

    float acc[2][NI][4];
#pragma unroll
    for (int mi = 0; mi < 2; mi++)
#pragma unroll
        for (int ni = 0; ni < NI; ni++)
#pragma unroll
            for (int e = 0; e < 4; e++) acc[mi][ni][e] = 0.f;

    auto gatherA = [&](int gr, int k) -> const float* {
        if (GATHER == 0) {
            return A1 + (size_t)gr * astride + k;
        } else {
            if (k < 256) return A1 + (size_t)gr * 256 + k;
            if (k < 512) return A2 + (size_t)gr * 256 + (k - 256);
            return A3 + (size_t)gr * 576 + (k - 512);
        }
    };

    auto loadStage = [&](int t, int st) {
        int kb = t * 32;
#pragma unroll
        for (int u = tid; u < BM * 8; u += NT) {
            int r = u >> 3, cq = u & 7;
            cpa16(smb + (((st * BM + r) * PADF + cq * 4) << 2), gatherA(row0 + r, kb + cq * 4));
        }
#pragma unroll
        for (int u = tid; u < BN * 8; u += NT) {
            int r = u >> 3, cq = u & 7;
            cpa16(smb + ((2 * BM * PADF + (st * BN + r) * PADF + cq * 4) << 2),
                  Bw + (size_t)r * bstride + kb + cq * 4);
        }
    };

    auto compute = [&](int st) {
        const float* At = Asm + st * BM * PADF;
        const float* Bt = Bsm + st * BN * PADF;
#pragma unroll
        for (int kk = 0; kk < 4; kk++) {
            uint32_t a[2][4], b[NI][2];
            const int k = kk * 8 + tq;
#pragma unroll
            for (int mi = 0; mi < 2; mi++) {
                int r = wm * 32 + mi * 16 + g;
                a[mi][0] = __float_as_uint(At[r * PADF + k]);
                a[mi][1] = __float_as_uint(At[(r + 8) * PADF + k]);
                a[mi][2] = __float_as_uint(At[r * PADF + k + 4]);
                a[mi][3] = __float_as_uint(At[(r + 8) * PADF + k + 4]);
            }
#pragma unroll
            for (int ni = 0; ni < NI; ni++) {
                int r = wn * (NI * 8) + ni * 8 + g;
                b[ni][0] = __float_as_uint(Bt[r * PADF + k]);
                b[ni][1] = __float_as_uint(Bt[r * PADF + k + 4]);
            }
#pragma unroll
            for (int mi = 0; mi < 2; mi++)
#pragma unroll
                for (int ni = 0; ni < NI; ni++)
                    mma_tf32(acc[mi][ni], a[mi], b[ni]);
        }
    };

    loadStage(0, 0); CP_COMMIT();
    for (int t = 0; t < NST; t++) {
        if (t + 1 < NST) { loadStage(t + 1, (t + 1) & 1); CP_COMMIT(); CP_WAIT(1); }
        else             { CP_WAIT(0); }
        __syncthreads();
        compute(t & 1);
        __syncthreads();
    }

    // ---------------- epilogues ----------------
    if (EPI == 0) {
#pragma unroll
        for (int mi = 0; mi < 2; mi++) {
            int r0 = row0 + wm * 32 + mi * 16 + g;
#pragma unroll
            for (int ni = 0; ni < NI; ni++) {
                int gc0 = col0 + wn * (NI * 8) + ni * 8 + tq * 2, gc1 = gc0 + 1;
                if (gc0 < N) {
                    float bv = bias ? bias[gc0] : 0.f;
                    Cf[(size_t)r0 * cstride + gc0]       = acc[mi][ni][0] + bv;
                    Cf[(size_t)(r0 + 8) * cstride + gc0] = acc[mi][ni][2] + bv;
                }
                if (gc1 < N) {
                    float bv = bias ? bias[gc1] : 0.f;
                    Cf[(size_t)r0 * cstride + gc1]       = acc[mi][ni][1] + bv;
                    Cf[(size_t)(r0 + 8) * cstride + gc1] = acc[mi][ni][3] + bv;
                }
            }
        }
        return;
    }

    // stat phase (EPI 1/2)
    float s[2][2] = {{0,0},{0,0}}, q[2][2] = {{0,0},{0,0}};
#pragma unroll
    for (int mi = 0; mi < 2; mi++)
#pragma unroll
        for (int ni = 0; ni < NI; ni++) {
            int c0 = wn * (NI * 8) + ni * 8 + tq * 2, c1 = c0 + 1;
            float b0v = (c0 < N) ? bias[c0] : 0.f;
            float b1v = (c1 < N) ? bias[c1] : 0.f;
            float v0 = acc[mi][ni][0] + b0v, v1 = acc[mi][ni][1] + b1v;
            float v2 = acc[mi][ni][2] + b0v, v3 = acc[mi][ni][3] + b1v;
            if (EPI == 2) {
                v0 = ftanh(v0); v1 = ftanh(v1); v2 = ftanh(v2); v3 = ftanh(v3);
            } else {
                v0 = fmaxf(v0, 0.f); v1 = fmaxf(v1, 0.f);
                v2 = fmaxf(v2, 0.f); v3 = fmaxf(v3, 0.f);
            }
            if (c0 >= N) { v0 = 0.f; v2 = 0.f; }
            if (c1 >= N) { v1 = 0.f; v3 = 0.f; }
            acc[mi][ni][0] = v0; acc[mi][ni][1] = v1;
            acc[mi][ni][2] = v2; acc[mi][ni][3] = v3;
            s[mi][0] += v0 + v1; q[mi][0] += v0 * v0 + v1 * v1;
            s[mi][1] += v2 + v3; q[mi][1] += v2 * v2 + v3 * v3;
        }
#pragma unroll
    for (int off = 1; off <= 2; off <<= 1)
#pragma unroll
        for (int mi = 0; mi < 2; mi++)
#pragma unroll
            for (int dr = 0; dr < 2; dr++) {
                s[mi][dr] += __shfl_xor_sync(0xffffffffu, s[mi][dr], off);
                q[mi][dr] += __shfl_xor_sync(0xffffffffu, q[mi][dr], off);
            }
    if (tq == 0)
#pragma unroll
        for (int mi = 0; mi < 2; mi++)
#pragma unroll
            for (int dr = 0; dr < 2; dr++) {
                int r = wm * 32 + mi * 16 + g + 8 * dr;
                red0[r * NWN + wn] = s[mi][dr];
                red1[r * NWN + wn] = q[mi][dr];
            }
    __syncthreads();
    float mu[2][2], rs[2][2];
    const float invN = 1.f / (float)N;
#pragma unroll
    for (int mi = 0; mi < 2; mi++)
#pragma unroll
        for (int dr = 0; dr < 2; dr++) {
            int r = wm * 32 + mi * 16 + g + 8 * dr;
            float ss = 0.f, qq = 0.f;
#pragma unroll
            for (int xx = 0; xx < NWN; xx++) { ss += red0[r * NWN + xx]; qq += red1[r * NWN + xx]; }
            mu[mi][dr] = ss * invN;
            rs[mi][dr] = rsqrtf(qq * invN - mu[mi][dr] * mu[mi][dr] + 1e-5f);
        }

    if (EPI == 1) {
#pragma unroll
        for (int mi = 0; mi < 2; mi++) {
            int gr0 = row0 + wm * 32 + mi * 16 + g;
#pragma unroll
            for (int ni = 0; ni < NI; ni++) {
                int c0 = wn * (NI * 8) + ni * 8 + tq * 2, c1 = c0 + 1;
                float g0 = (c0 < N) ? gamma[c0] : 0.f, g1 = (c1 < N) ? gamma[c1] : 0.f;
                float t0 = (c0 < N) ? beta[c0] : 0.f,  t1 = (c1 < N) ? beta[c1]  : 0.f;
#pragma unroll
                for (int dr = 0; dr < 2; dr++) {
                    int gr = gr0 + 8 * dr;
                    float w0 = (c0 < N) ? (acc[mi][ni][2*dr+0] - mu[mi][dr]) * rs[mi][dr] * g0 + t0 : 0.f;
                    float w1 = (c1 < N) ? (acc[mi][ni][2*dr+1] - mu[mi][dr]) * rs[mi][dr] * g1 + t1 : 0.f;
                    float2 wv = make_float2(tf32r(w0), tf32r(w1));
                    *(float2*)(Cpl + (size_t)gr * 256 + c0) = wv;
                }
            }
        }
        return;
    }

    // EPI == 2
    {
        float d[2][2] = {{0,0},{0,0}};
#pragma unroll
        for (int mi = 0; mi < 2; mi++)
#pragma unroll
            for (int ni = 0; ni < NI; ni++) {
                int c0 = wn * (NI * 8) + ni * 8 + tq * 2, c1 = c0 + 1;
#pragma unroll
                for (int dr = 0; dr < 2; dr++) {
                    if (c0 < N)
                        d[mi][dr] += ((acc[mi][ni][2*dr+0] - mu[mi][dr]) * rs[mi][dr] * gamma[c0] + beta[c0]) * W2[c0];
                    if (c1 < N)
                        d[mi][dr] += ((acc[mi][ni][2*dr+1] - mu[mi][dr]) * rs[mi][dr] * gamma[c1] + beta[c1]) * W2[c1];
                }
            }
#pragma unroll
        for (int off = 1; off <= 2; off <<= 1)
#pragma unroll
            for (int mi = 0; mi < 2; mi++)
#pragma unroll
                for (int dr = 0; dr < 2; dr++)
                    d[mi][dr] += __shfl_xor_sync(0xffffffffu, d[mi][dr], off);
        __syncthreads();
        if (tq == 0)
#pragma unroll
            for (int mi = 0; mi < 2; mi++)
#pragma unroll
                for (int dr = 0; dr < 2; dr++) {
                    int r = wm * 32 + mi * 16 + g + 8 * dr;
                    red0[r * NWN + wn] = d[mi][dr];
                }
        __syncthreads();
        if (wn == 0 && tq == 0) {
            float bb = b2[0];
#pragma unroll
            for (int mi = 0; mi < 2; mi++)
#pragma unroll
                for (int dr = 0; dr < 2; dr++) {
                    int r = wm * 32 + mi * 16 + g + 8 * dr;
                    float dd = 0.f;
#pragma unroll
                    for (int xx = 0; xx < NWN; xx++) dd += red0[r * NWN + xx];
                    Cf[row0 + r] = fsigmoid(dd + bb);
                }
        }
    }
}

// ---------------- core combine: core[b,i,j] = LN(relu(U[b,i] + V[b,j] + bias)) ----------------
__global__ void __launch_bounds__(256) combine_core(
    const float* __restrict__ UV, const float* __restrict__ bias,
    const float* __restrict__ gamma, const float* __restrict__ beta,
    float* __restrict__ core)
{
    const int r    = blockIdx.x * 8 + (threadIdx.x >> 5);
    const int lane = threadIdx.x & 31;
    const int b = r / 56, rem = r - b * 56;
    const int i = rem / 7, jj = rem - i * 7;
    const int j = jj + (jj >= i ? 1 : 0);
    const float4* up = (const float4*)(UV + (size_t)(b * 8 + i) * 512);
    const float4* vp = (const float4*)(UV + (size_t)(b * 8 + j) * 512 + 256);

    const int c0 = lane * 8;
    float v[8];
#pragma unroll
    for (int h = 0; h < 2; h++) {
        float4 u4 = up[lane * 2 + h];
        float4 v4 = vp[lane * 2 + h];
        float* vv = v + h * 4;
        vv[0] = u4.x + v4.x; vv[1] = u4.y + v4.y;
        vv[2] = u4.z + v4.z; vv[3] = u4.w + v4.w;
    }
    float s = 0.f, q = 0.f;
#pragma unroll
    for (int e = 0; e < 8; e++) {
        int c = c0 + e;
        float x = (c < 250) ? fmaxf(v[e] + bias[c], 0.f) : 0.f;
        v[e] = x;
        s += x; q += x * x;
    }
#pragma unroll
    for (int off = 16; off > 0; off >>= 1) {
        s += __shfl_xor_sync(0xffffffffu, s, off);
        q += __shfl_xor_sync(0xffffffffu, q, off);
    }
    float mu = s * (1.f / 250.f);
    float rs = rsqrtf(q * (1.f / 250.f) - mu * mu + 1e-5f);

    float4 o0, o1;
#pragma unroll
    for (int e = 0; e < 8; e++) {
        int c = c0 + e;
        float w = (c < 250) ? (v[e] - mu) * rs * gamma[c] + beta[c] : 0.f;
        ((e < 4) ? (&o0.x) : (&o1.x))[e & 3] = tf32r(w);
    }
    float4* dst = (float4*)(core + (size_t)r * 256 + c0);
    dst[0] = o0; dst[1] = o1;
}

// effect: eff[bk][c] = sum_j ctx[bk*7+j][c] * att[bk*7+j], tf32-rounded
__global__ void effect3(const float* __restrict__ cx, const float* __restrict__ att,
                        float* __restrict__ eff)
{
    int bk = blockIdx.x, c = threadIdx.x;
    __shared__ float a[7];
    if (c < 7) a[c] = att[bk * 7 + c];
    __syncthreads();
    size_t base = (size_t)bk * 7 * 256 + c;
    float s = 0.f;
#pragma unroll
    for (int j = 0; j < 7; j++) s = fmaf(cx[base + j * 256], a[j], s);
    eff[(size_t)bk * 256 + c] = tf32r(s);
}

extern "C" void kernel_launch(void* const* d_in, const int* in_sizes, int n_in,
                              void* d_out, int out_size)
{
    const float* x       = (const float*)d_in[0];
    const float* state   = (const float*)d_in[1];
    const float* enc_W   = (const float*)d_in[2];
    const float* enc_b   = (const float*)d_in[3];
    const float* enc_g   = (const float*)d_in[4];
    const float* enc_bt  = (const float*)d_in[5];
    const float* core_W  = (const float*)d_in[6];
    const float* core_b  = (const float*)d_in[7];
    const float* core_g  = (const float*)d_in[8];
    const float* core_bt = (const float*)d_in[9];
    const float* ctx_W   = (const float*)d_in[10];
    const float* ctx_b   = (const float*)d_in[11];
    const float* ctx_g   = (const float*)d_in[12];
    const float* ctx_bt  = (const float*)d_in[13];
    const float* att_W1  = (const float*)d_in[14];
    const float* att_b1  = (const float*)d_in[15];
    const float* att_g   = (const float*)d_in[16];
    const float* att_bt  = (const float*)d_in[17];
    const float* att_W2  = (const float*)d_in[18];
    const float* att_b2  = (const float*)d_in[19];
    const float* out_W   = (const float*)d_in[20];
    const float* out_b   = (const float*)d_in[21];
    float* out = (float*)d_out;

    float *sp, *xp, *s1, *uv, *co, *cx, *att, *ef, *eW, *uvW, *xW, *aW, *oW;
    cudaGetSymbolAddress((void**)&sp, g_sp);   cudaGetSymbolAddress((void**)&xp, g_xp);
    cudaGetSymbolAddress((void**)&s1, g_s1);   cudaGetSymbolAddress((void**)&uv, g_uv);
    cudaGetSymbolAddress((void**)&co, g_co);   cudaGetSymbolAddress((void**)&cx, g_cx);
    cudaGetSymbolAddress((void**)&att, g_att); cudaGetSymbolAddress((void**)&ef, g_ef);
    cudaGetSymbolAddress((void**)&eW, g_eW);   cudaGetSymbolAddress((void**)&uvW, g_uvW);
    cudaGetSymbolAddress((void**)&xW, g_xW);   cudaGetSymbolAddress((void**)&aW, g_aW);
    cudaGetSymbolAddress((void**)&oW, g_oW);

    const int SM_STD = 2 * (64 + 256) * 36 * 4 + 2 * 64 * 4 * 4;       // 94208  (BM64/BN256, NT256)
    const int SM_BIG = 2 * (128 + 256) * 36 * 4 + 2 * 128 * 4 * 4;     // 114688 (BM128/BN256, NT512)
    const int SM_ATT = 2 * (256 + 128) * 36 * 4 + 2 * 256 * 2 * 4;     // 114688 (BM256/BN128, NT512)
    cudaFuncSetAttribute((const void*)tgemm<64, 256, 256, 256, 0, 1>,    cudaFuncAttributeMaxDynamicSharedMemorySize, SM_STD);
    cudaFuncSetAttribute((const void*)tgemm<64, 256, 256, 256, 0, 0>,    cudaFuncAttributeMaxDynamicSharedMemorySize, SM_STD);
    cudaFuncSetAttribute((const void*)tgemm<128, 256, 512, 256, 0, 1>,   cudaFuncAttributeMaxDynamicSharedMemorySize, SM_BIG);
    cudaFuncSetAttribute((const void*)tgemm<256, 128, 512, 256, 0, 2>,   cudaFuncAttributeMaxDynamicSharedMemorySize, SM_ATT);
    cudaFuncSetAttribute((const void*)tgemm<128, 256, 512, 1088, 2, 0>,  cudaFuncAttributeMaxDynamicSharedMemorySize, SM_BIG);

    // ---- prep ----
    cvt_pad<<<(16384 * 256) / 256, 256>>>(sp, 256, state, 250, 16384);
    cvt_pad<<<(16384 * 576) / 256, 256>>>(xp, 576, x, 576, 16384);

    PrepJobs J;
    auto mk = [](float* dst, const float* W, int Kp, int N0,
                 int b0, int v0, int b1, int v1, int b2, int v2, int NP) {
        PrepJob p; p.dst = dst; p.W = W; p.Kp = Kp; p.N0 = N0;
        p.b0 = b0; p.v0 = v0; p.b1 = b1; p.v1 = v1; p.b2 = b2; p.v2 = v2;
        p.count = NP * Kp; return p;
    };
    J.j[0] = mk(eW,              enc_W,  256, 250, 0, 250, 0, 0, 0, 0, 256);
    J.j[1] = mk(uvW,             core_W, 256, 250, 0, 250, 0, 0, 0, 0, 256);
    J.j[2] = mk(uvW + 256 * 256, core_W, 256, 250, 250, 250, 0, 0, 0, 0, 256);
    J.j[3] = mk(xW,              ctx_W,  256, 250, 0, 250, 0, 0, 0, 0, 256);
    J.j[4] = mk(aW,              att_W1, 256, 100, 0, 250, 0, 0, 0, 0, 128);
    J.j[5] = mk(oW,              out_W,  1088, 250, 0, 250, 250, 250, 500, 576, 256);
    J.cum[0] = 0;
    for (int i = 0; i < 6; i++) J.cum[i + 1] = J.cum[i] + J.j[i].count;
    prep_all<<<(J.cum[6] + 255) / 256, 256>>>(J);

    // 1. enc: s1 = LN(relu(state @ enc_W + b))  [tf32 plane]
    tgemm<64, 256, 256, 256, 0, 1><<<BKTOT / 64, 256, SM_STD>>>(
        sp, nullptr, nullptr, eW,
        enc_b, enc_g, enc_bt, nullptr, nullptr,
        nullptr, s1, 250, 256, 256, 0);
    // 2. UV = s1 @ [W_top ++ W_bot]  (fp32, grid.y = 2)
    tgemm<64, 256, 256, 256, 0, 0><<<dim3(BKTOT / 64, 2), 256, SM_STD>>>(
        s1, nullptr, nullptr, uvW,
        nullptr, nullptr, nullptr, nullptr, nullptr,
        uv, nullptr, 512, 256, 256, 512);
    // 3. core[b,i,j] = LN(relu(U[b,i] + V[b,j] + core_b))  [tf32 plane]
    combine_core<<<RR / 8, 256>>>(uv, core_b, core_g, core_bt, co);
    // 4. ctx = LN(relu(core @ ctx_W))  [tf32 plane]  — BIG tile, 512 thr
    tgemm<128, 256, 512, 256, 0, 1><<<RR / 128, 512, SM_BIG>>>(
        co, nullptr, nullptr, xW,
        ctx_b, ctx_g, ctx_bt, nullptr, nullptr,
        nullptr, cx, 250, 256, 256, 0);
    // 5. att scores — BM=256, 512 thr
    tgemm<256, 128, 512, 256, 0, 2><<<RR / 256, 512, SM_ATT>>>(
        co, nullptr, nullptr, aW,
        att_b1, att_g, att_bt, att_W2, att_b2,
        att, nullptr, 100, 256, 256, 0);
    // 6. attention-weighted reduction
    effect3<<<BKTOT, 256>>>(cx, att, ef);
    // 7. out: [s1 | eff | x] @ out_W + b — BIG tile, 512 thr
    tgemm<128, 256, 512, 1088, 2, 0><<<BKTOT / 128, 512, SM_BIG>>>(
        s1, ef, xp, oW,
        out_b, nullptr, nullptr, nullptr, nullptr,
        out, nullptr, 250, 0, 1088, 250);
}

// round 15
// speedup vs baseline: 1.0246x; 1.0246x over previous
#include <cuda_runtime.h>
#include <cuda_bf16.h>
#include <math.h>
#include <stdint.h>

static constexpr int BKTOT = 16384;
static constexpr int RR    = 114688;

// ---------------- device-global scratch (allocation-free), fp32 tf32-prerounded ----
__device__ __align__(16) float g_sp [16384*256];
__device__ __align__(16) float g_xp [16384*576];
__device__ __align__(16) float g_s1 [16384*256];
__device__ __align__(16) float g_uv [16384*512];
__device__ __align__(16) float g_mu [114688];
__device__ __align__(16) float g_rs [114688];
__device__ __align__(16) float g_cx [114688*256];
__device__ __align__(16) float g_att[114688];
__device__ __align__(16) float g_ef [16384*256];
__device__ __align__(16) float g_eW [256*256];
__device__ __align__(16) float g_uvW[512*256];
__device__ __align__(16) float g_xW [256*256];
__device__ __align__(16) float g_aW [128*256];
__device__ __align__(16) float g_oW [256*1088];

// ---------------- helpers ----------------
__device__ __forceinline__ uint32_t smem_u32(const void* p) {
    uint32_t a;
    asm("{ .reg .u64 t; cvta.to.shared.u64 t, %1; cvt.u32.u64 %0, t; }" : "=r"(a) : "l"(p));
    return a;
}
__device__ __forceinline__ void cpa16(uint32_t saddr, const void* g) {
    asm volatile("cp.async.cg.shared.global [%0], [%1], 16;" :: "r"(saddr), "l"(g));
}
#define CP_COMMIT() asm volatile("cp.async.commit_group;" ::: "memory")
#define CP_WAIT(n)  asm volatile("cp.async.wait_group %0;" :: "n"(n) : "memory")

__device__ __forceinline__ float tf32r(float x) {
    uint32_t r;
    asm("cvt.rna.tf32.f32 %0, %1;" : "=r"(r) : "f"(x));
    return __uint_as_float(r);
}
__device__ __forceinline__ void mma_tf32(float* d, const uint32_t* a, const uint32_t* b) {
    asm volatile(
        "mma.sync.aligned.m16n8k8.row.col.f32.tf32.tf32.f32 "
        "{%0,%1,%2,%3}, {%4,%5,%6,%7}, {%8,%9}, {%0,%1,%2,%3};"
        : "+f"(d[0]), "+f"(d[1]), "+f"(d[2]), "+f"(d[3])
        : "r"(a[0]), "r"(a[1]), "r"(a[2]), "r"(a[3]), "r"(b[0]), "r"(b[1]));
}
__device__ __forceinline__ float ftanh(float x) {
    float t = fminf(fmaxf(2.f * x, -30.f), 30.f);
    float e = __expf(t);
    return (e - 1.f) / (e + 1.f);
}
__device__ __forceinline__ float fsigmoid(float z) { return 1.f / (1.f + __expf(-z)); }

// ---------------- prep kernels ----------------
__global__ void cvt_pad(float* __restrict__ dst, int DS,
                        const float* __restrict__ src, int SC, int rows)
{
    int idx = blockIdx.x * blockDim.x + threadIdx.x;
    if (idx >= rows * DS) return;
    int r = idx / DS, c = idx - r * DS;
    float v = (c < SC) ? src[(size_t)r * SC + c] : 0.f;
    dst[idx] = tf32r(v);
}

struct PrepJob {
    float* dst;
    const float* W;
    int Kp, N0;
    int b0, v0, b1, v1, b2, v2;
    int count;
};
struct PrepJobs { PrepJob j[6]; int cum[7]; };

__global__ void prep_all(PrepJobs J)
{
    int e = blockIdx.x * blockDim.x + threadIdx.x;
    if (e >= J.cum[6]) return;
    int ji = 0;
    while (e >= J.cum[ji + 1]) ji++;
    const PrepJob& p = J.j[ji];
    int idx = e - J.cum[ji];
    int n = idx / p.Kp, k = idx - n * p.Kp;
    int piece = (k >= 512) ? 2 : (k >= 256) ? 1 : 0;
    int off = k - ((piece == 2) ? 512 : piece * 256);
    int base  = (piece == 0) ? p.b0 : (piece == 1) ? p.b1 : p.b2;
    int valid = (piece == 0) ? p.v0 : (piece == 1) ? p.v1 : p.v2;
    float v = (off < valid && n < p.N0) ? p.W[(size_t)(base + off) * p.N0 + n] : 0.f;
    p.dst[idx] = tf32r(v);
}

// ---------------- LN row stats for the virtual core plane ----------------
// mu/rs per pair-row, computed EXACTLY as combine_core did (bitwise-stable).
__global__ void __launch_bounds__(256) ln_stats(
    const float* __restrict__ UV, const float* __restrict__ bias,
    float* __restrict__ MU, float* __restrict__ RS)
{
    const int r    = blockIdx.x * 8 + (threadIdx.x >> 5);
    const int lane = threadIdx.x & 31;
    const int b = r / 56, rem = r - b * 56;
    const int i = rem / 7, jj = rem - i * 7;
    const int j = jj + (jj >= i ? 1 : 0);
    const float4* up = (const float4*)(UV + (size_t)(b * 8 + i) * 512);
    const float4* vp = (const float4*)(UV + (size_t)(b * 8 + j) * 512 + 256);

    const int c0 = lane * 8;
    float v[8];
#pragma unroll
    for (int h = 0; h < 2; h++) {
        float4 u4 = up[lane * 2 + h];
        float4 v4 = vp[lane * 2 + h];
        float* vv = v + h * 4;
        vv[0] = u4.x + v4.x; vv[1] = u4.y + v4.y;
        vv[2] = u4.z + v4.z; vv[3] = u4.w + v4.w;
    }
    float s = 0.f, q = 0.f;
#pragma unroll
    for (int e = 0; e < 8; e++) {
        int c = c0 + e;
        float x = (c < 250) ? fmaxf(v[e] + bias[c], 0.f) : 0.f;
        s += x; q += x * x;
    }
#pragma unroll
    for (int off = 16; off > 0; off >>= 1) {
        s += __shfl_xor_sync(0xffffffffu, s, off);
        q += __shfl_xor_sync(0xffffffffu, q, off);
    }
    float mu = s * (1.f / 250.f);
    float rsv = rsqrtf(q * (1.f / 250.f) - mu * mu + 1e-5f);
    if (lane == 0) { MU[r] = mu; RS[r] = rsv; }
}

// ---------------- TF32 fused GEMM (2-stage double buffer, BK=32) ----------------
// GATHER: 0 plain (astride); 2 [s1|eff|x]; 3 virtual core from UV (+MU/RS/lnC consts)
// EPI: 0 bias?+fp32 store; 1 relu+LN -> tf32 plane; 2 tanh+LN+dot(W2)+sigmoid -> scalar
template<int BM, int BN, int KTOT, int GATHER, int EPI>
__global__ void __launch_bounds__(256) tgemm(
    const float* __restrict__ A1, const float* __restrict__ A2, const float* __restrict__ A3,
    const float* __restrict__ Bw,
    const float* __restrict__ bias, const float* __restrict__ gamma, const float* __restrict__ beta,
    const float* __restrict__ W2, const float* __restrict__ b2,
    const float* __restrict__ MU, const float* __restrict__ RS,
    const float* __restrict__ Gb, const float* __restrict__ Gg, const float* __restrict__ Gt,
    float* __restrict__ Cf, float* __restrict__ Cpl,
    int N, int astride, int bstride, int cstride)
{
    constexpr int PADF = 36;
    constexpr int NWM = BM / 32;
    constexpr int NWN = 8 / NWM;
    constexpr int NI  = BN / (8 * NWN);
    constexpr int NST = KTOT / 32;

    extern __shared__ __align__(16) float sm[];
    float* const Asm = sm;
    float* const Bsm = sm + 2 * BM * PADF;
    float* const red0 = sm + 2 * (BM + BN) * PADF;
    float* const red1 = red0 + BM * NWN;
    float* const lnC  = red1 + BM * NWN;   // GATHER==3: [cb|cg|ct] 3*256 floats
    const uint32_t smb = smem_u32(sm);

    const int tid = threadIdx.x, w = tid >> 5, lane = tid & 31;
    const int g = lane >> 2, tq = lane & 3;
    const int wm = w % NWM, wn = w / NWM;
    const int row0 = blockIdx.x * BM;
    const int col0 = blockIdx.y * BN;
    Bw += (size_t)col0 * bstride;

    if (GATHER == 3) {
        if (tid < 256) {
            lnC[tid]       = (tid < 250) ? Gb[tid] : 0.f;
            lnC[256 + tid] = (tid < 250) ? Gg[tid] : 0.f;
            lnC[512 + tid] = (tid < 250) ? Gt[tid] : 0.f;
        }
        __syncthreads();
    }

    float acc[2][NI][4];
#pragma unroll
    for (int mi = 0; mi < 2; mi++)
#pragma unroll
        for (int ni = 0; ni < NI; ni++)
#pragma unroll
            for (int e = 0; e < 4; e++) acc[mi][ni][e] = 0.f;

    auto gatherA = [&](int gr, int k) -> const float* {
        if (GATHER == 0) {
            return A1 + (size_t)gr * astride + k;
        } else {
            if (k < 256) return A1 + (size_t)gr * 256 + k;
            if (k < 512) return A2 + (size_t)gr * 256 + (k - 256);
            return A3 + (size_t)gr * 576 + (k - 512);
        }
    };

    auto loadStage = [&](int t, int st) {
        int kb = t * 32;
        if (GATHER == 3) {
            // synthesize A tile: core[gr][k] from UV + row stats + LN consts
#pragma unroll
            for (int u = tid; u < BM * 8; u += 256) {
                int r = u >> 3, cq = u & 7;
                int gr = row0 + r;
                int k0 = kb + cq * 4;
                int b = gr / 56, rem = gr - b * 56;
                int i = rem / 7, jj = rem - i * 7;
                int j = jj + (jj >= i ? 1 : 0);
                float4 uu = *(const float4*)(A1 + (size_t)(b * 8 + i) * 512 + k0);
                float4 vv = *(const float4*)(A1 + (size_t)(b * 8 + j) * 512 + 256 + k0);
                float m = MU[gr], rsv = RS[gr];
                float4 o;
                {
                    float x0 = fmaxf(uu.x + vv.x + lnC[k0 + 0], 0.f);
                    float x1 = fmaxf(uu.y + vv.y + lnC[k0 + 1], 0.f);
                    float x2 = fmaxf(uu.z + vv.z + lnC[k0 + 2], 0.f);
                    float x3 = fmaxf(uu.w + vv.w + lnC[k0 + 3], 0.f);
                    o.x = tf32r((x0 - m) * rsv * lnC[256 + k0 + 0] + lnC[512 + k0 + 0]);
                    o.y = tf32r((x1 - m) * rsv * lnC[256 + k0 + 1] + lnC[512 + k0 + 1]);
                    o.z = tf32r((x2 - m) * rsv * lnC[256 + k0 + 2] + lnC[512 + k0 + 2]);
                    o.w = tf32r((x3 - m) * rsv * lnC[256 + k0 + 3] + lnC[512 + k0 + 3]);
                }
                *(float4*)&Asm[(st * BM + r) * PADF + cq * 4] = o;
            }
        } else {
#pragma unroll
            for (int u = tid; u < BM * 8; u += 256) {
                int r = u >> 3, cq = u & 7;
                cpa16(smb + (((st * BM + r) * PADF + cq * 4) << 2), gatherA(row0 + r, kb + cq * 4));
            }
        }
#pragma unroll
        for (int u = tid; u < BN * 8; u += 256) {
            int r = u >> 3, cq = u & 7;
            cpa16(smb + ((2 * BM * PADF + (st * BN + r) * PADF + cq * 4) << 2),
                  Bw + (size_t)r * bstride + kb + cq * 4);
        }
    };

    auto compute = [&](int st) {
        const float* At = Asm + st * BM * PADF;
        const float* Bt = Bsm + st * BN * PADF;
#pragma unroll
        for (int kk = 0; kk < 4; kk++) {
            uint32_t a[2][4], b[NI][2];
            const int k = kk * 8 + tq;
#pragma unroll
            for (int mi = 0; mi < 2; mi++) {
                int r = wm * 32 + mi * 16 + g;
                a[mi][0] = __float_as_uint(At[r * PADF + k]);
                a[mi][1] = __float_as_uint(At[(r + 8) * PADF + k]);
                a[mi][2] = __float_as_uint(At[r * PADF + k + 4]);
                a[mi][3] = __float_as_uint(At[(r + 8) * PADF + k + 4]);
            }
#pragma unroll
            for (int ni = 0; ni < NI; ni++) {
                int r = wn * (NI * 8) + ni * 8 + g;
                b[ni][0] = __float_as_uint(Bt[r * PADF + k]);
                b[ni][1] = __float_as_uint(Bt[r * PADF + k + 4]);
            }
#pragma unroll
            for (int mi = 0; mi < 2; mi++)
#pragma unroll
                for (int ni = 0; ni < NI; ni++)
                    mma_tf32(acc[mi][ni], a[mi], b[ni]);
        }
    };

    loadStage(0, 0); CP_COMMIT();
    for (int t = 0; t < NST; t++) {
        if (t + 1 < NST) { loadStage(t + 1, (t + 1) & 1); CP_COMMIT(); CP_WAIT(1); }
        else             { CP_WAIT(0); }
        __syncthreads();
        compute(t & 1);
        __syncthreads();
    }

    // ---------------- epilogues ----------------
    if (EPI == 0) {
#pragma unroll
        for (int mi = 0; mi < 2; mi++) {
            int r0 = row0 + wm * 32 + mi * 16 + g;
#pragma unroll
            for (int ni = 0; ni < NI; ni++) {
                int gc0 = col0 + wn * (NI * 8) + ni * 8 + tq * 2, gc1 = gc0 + 1;
                if (gc0 < N) {
                    float bv = bias ? bias[gc0] : 0.f;
                    Cf[(size_t)r0 * cstride + gc0]       = acc[mi][ni][0] + bv;
                    Cf[(size_t)(r0 + 8) * cstride + gc0] = acc[mi][ni][2] + bv;
                }
                if (gc1 < N) {
                    float bv = bias ? bias[gc1] : 0.f;
                    Cf[(size_t)r0 * cstride + gc1]       = acc[mi][ni][1] + bv;
                    Cf[(size_t)(r0 + 8) * cstride + gc1] = acc[mi][ni][3] + bv;
                }
            }
        }
        return;
    }

    // stat phase (EPI 1/2)
    float s[2][2] = {{0,0},{0,0}}, q[2][2] = {{0,0},{0,0}};
#pragma unroll
    for (int mi = 0; mi < 2; mi++)
#pragma unroll
        for (int ni = 0; ni < NI; ni++) {
            int c0 = wn * (NI * 8) + ni * 8 + tq * 2, c1 = c0 + 1;
            float b0v = (c0 < N) ? bias[c0] : 0.f;
            float b1v = (c1 < N) ? bias[c1] : 0.f;
            float v0 = acc[mi][ni][0] + b0v, v1 = acc[mi][ni][1] + b1v;
            float v2 = acc[mi][ni][2] + b0v, v3 = acc[mi][ni][3] + b1v;
            if (EPI == 2) {
                v0 = ftanh(v0); v1 = ftanh(v1); v2 = ftanh(v2); v3 = ftanh(v3);
            } else {
                v0 = fmaxf(v0, 0.f); v1 = fmaxf(v1, 0.f);
                v2 = fmaxf(v2, 0.f); v3 = fmaxf(v3, 0.f);
            }
            if (c0 >= N) { v0 = 0.f; v2 = 0.f; }
            if (c1 >= N) { v1 = 0.f; v3 = 0.f; }
            acc[mi][ni][0] = v0; acc[mi][ni][1] = v1;
            acc[mi][ni][2] = v2; acc[mi][ni][3] = v3;
            s[mi][0] += v0 + v1; q[mi][0] += v0 * v0 + v1 * v1;
            s[mi][1] += v2 + v3; q[mi][1] += v2 * v2 + v3 * v3;
        }
#pragma unroll
    for (int off = 1; off <= 2; off <<= 1)
#pragma unroll
        for (int mi = 0; mi < 2; mi++)
#pragma unroll
            for (int dr = 0; dr < 2; dr++) {
                s[mi][dr] += __shfl_xor_sync(0xffffffffu, s[mi][dr], off);
                q[mi][dr] += __shfl_xor_sync(0xffffffffu, q[mi][dr], off);
            }
    if (tq == 0)
#pragma unroll
        for (int mi = 0; mi < 2; mi++)
#pragma unroll
            for (int dr = 0; dr < 2; dr++) {
                int r = wm * 32 + mi * 16 + g + 8 * dr;
                red0[r * NWN + wn] = s[mi][dr];
                red1[r * NWN + wn] = q[mi][dr];
            }
    __syncthreads();
    float mu[2][2], rs[2][2];
    const float invN = 1.f / (float)N;
#pragma unroll
    for (int mi = 0; mi < 2; mi++)
#pragma unroll
        for (int dr = 0; dr < 2; dr++) {
            int r = wm * 32 + mi * 16 + g + 8 * dr;
            float ss = 0.f, qq = 0.f;
#pragma unroll
            for (int xx = 0; xx < NWN; xx++) { ss += red0[r * NWN + xx]; qq += red1[r * NWN + xx]; }
            mu[mi][dr] = ss * invN;
            rs[mi][dr] = rsqrtf(qq * invN - mu[mi][dr] * mu[mi][dr] + 1e-5f);
        }

    if (EPI == 1) {
#pragma unroll
        for (int mi = 0; mi < 2; mi++) {
            int gr0 = row0 + wm * 32 + mi * 16 + g;
#pragma unroll
            for (int ni = 0; ni < NI; ni++) {
                int c0 = wn * (NI * 8) + ni * 8 + tq * 2, c1 = c0 + 1;
                float g0 = (c0 < N) ? gamma[c0] : 0.f, g1 = (c1 < N) ? gamma[c1] : 0.f;
                float t0 = (c0 < N) ? beta[c0] : 0.f,  t1 = (c1 < N) ? beta[c1]  : 0.f;
#pragma unroll
                for (int dr = 0; dr < 2; dr++) {
                    int gr = gr0 + 8 * dr;
                    float w0 = (c0 < N) ? (acc[mi][ni][2*dr+0] - mu[mi][dr]) * rs[mi][dr] * g0 + t0 : 0.f;
                    float w1 = (c1 < N) ? (acc[mi][ni][2*dr+1] - mu[mi][dr]) * rs[mi][dr] * g1 + t1 : 0.f;
                    float2 wv = make_float2(tf32r(w0), tf32r(w1));
                    *(float2*)(Cpl + (size_t)gr * 256 + c0) = wv;
                }
            }
        }
        return;
    }

    // EPI == 2
    {
        float d[2][2] = {{0,0},{0,0}};
#pragma unroll
        for (int mi = 0; mi < 2; mi++)
#pragma unroll
            for (int ni = 0; ni < NI; ni++) {
                int c0 = wn * (NI * 8) + ni * 8 + tq * 2, c1 = c0 + 1;
#pragma unroll
                for (int dr = 0; dr < 2; dr++) {
                    if (c0 < N)
                        d[mi][dr] += ((acc[mi][ni][2*dr+0] - mu[mi][dr]) * rs[mi][dr] * gamma[c0] + beta[c0]) * W2[c0];
                    if (c1 < N)
                        d[mi][dr] += ((acc[mi][ni][2*dr+1] - mu[mi][dr]) * rs[mi][dr] * gamma[c1] + beta[c1]) * W2[c1];
                }
            }
#pragma unroll
        for (int off = 1; off <= 2; off <<= 1)
#pragma unroll
            for (int mi = 0; mi < 2; mi++)
#pragma unroll
                for (int dr = 0; dr < 2; dr++)
                    d[mi][dr] += __shfl_xor_sync(0xffffffffu, d[mi][dr], off);
        __syncthreads();
        if (tq == 0)
#pragma unroll
            for (int mi = 0; mi < 2; mi++)
#pragma unroll
                for (int dr = 0; dr < 2; dr++) {
                    int r = wm * 32 + mi * 16 + g + 8 * dr;
                    red0[r * NWN + wn] = d[mi][dr];
                }
        __syncthreads();
        if (wn == 0 && tq == 0) {
            float bb = b2[0];
#pragma unroll
            for (int mi = 0; mi < 2; mi++)
#pragma unroll
                for (int dr = 0; dr < 2; dr++) {
                    int r = wm * 32 + mi * 16 + g + 8 * dr;
                    float dd = 0.f;
#pragma unroll
                    for (int xx = 0; xx < NWN; xx++) dd += red0[r * NWN + xx];
                    Cf[row0 + r] = fsigmoid(dd + bb);
                }
        }
    }
}

// effect: eff[bk][c] = sum_j ctx[bk*7+j][c] * att[bk*7+j], tf32-rounded
__global__ void effect3(const float* __restrict__ cx, const float* __restrict__ att,
                        float* __restrict__ eff)
{
    int bk = blockIdx.x, c = threadIdx.x;
    __shared__ float a[7];
    if (c < 7) a[c] = att[bk * 7 + c];
    __syncthreads();
    size_t base = (size_t)bk * 7 * 256 + c;
    float s = 0.f;
#pragma unroll
    for (int j = 0; j < 7; j++) s = fmaf(cx[base + j * 256], a[j], s);
    eff[(size_t)bk * 256 + c] = tf32r(s);
}

extern "C" void kernel_launch(void* const* d_in, const int* in_sizes, int n_in,
                              void* d_out, int out_size)
{
    const float* x       = (const float*)d_in[0];
    const float* state   = (const float*)d_in[1];
    const float* enc_W   = (const float*)d_in[2];
    const float* enc_b   = (const float*)d_in[3];
    const float* enc_g   = (const float*)d_in[4];
    const float* enc_bt  = (const float*)d_in[5];
    const float* core_W  = (const float*)d_in[6];
    const float* core_b  = (const float*)d_in[7];
    const float* core_g  = (const float*)d_in[8];
    const float* core_bt = (const float*)d_in[9];
    const float* ctx_W   = (const float*)d_in[10];
    const float* ctx_b   = (const float*)d_in[11];
    const float* ctx_g   = (const float*)d_in[12];
    const float* ctx_bt  = (const float*)d_in[13];
    const float* att_W1  = (const float*)d_in[14];
    const float* att_b1  = (const float*)d_in[15];
    const float* att_g   = (const float*)d_in[16];
    const float* att_bt  = (const float*)d_in[17];
    const float* att_W2  = (const float*)d_in[18];
    const float* att_b2  = (const float*)d_in[19];
    const float* out_W   = (const float*)d_in[20];
    const float* out_b   = (const float*)d_in[21];
    float* out = (float*)d_out;

    float *sp, *xp, *s1, *uv, *mu, *rsb, *cx, *att, *ef, *eW, *uvW, *xW, *aW, *oW;
    cudaGetSymbolAddress((void**)&sp, g_sp);   cudaGetSymbolAddress((void**)&xp, g_xp);
    cudaGetSymbolAddress((void**)&s1, g_s1);   cudaGetSymbolAddress((void**)&uv, g_uv);
    cudaGetSymbolAddress((void**)&mu, g_mu);   cudaGetSymbolAddress((void**)&rsb, g_rs);
    cudaGetSymbolAddress((void**)&cx, g_cx);   cudaGetSymbolAddress((void**)&att, g_att);
    cudaGetSymbolAddress((void**)&ef, g_ef);   cudaGetSymbolAddress((void**)&eW, g_eW);
    cudaGetSymbolAddress((void**)&uvW, g_uvW); cudaGetSymbolAddress((void**)&xW, g_xW);
    cudaGetSymbolAddress((void**)&aW, g_aW);   cudaGetSymbolAddress((void**)&oW, g_oW);

    const int SM_STD  = 2 * (64 + 256) * 36 * 4 + 2 * 64 * 4 * 4;              // 94208
    const int SM_STDG = SM_STD + 768 * 4;                                      // 97280 (GATHER=3)
    const int SM_ATT  = 2 * (128 + 128) * 36 * 4 + 2 * 128 * 2 * 4;            // 75776
    const int SM_ATTG = SM_ATT + 768 * 4;                                      // 78848
    cudaFuncSetAttribute((const void*)tgemm<64, 256, 256, 0, 1>,   cudaFuncAttributeMaxDynamicSharedMemorySize, SM_STD);
    cudaFuncSetAttribute((const void*)tgemm<64, 256, 256, 0, 0>,   cudaFuncAttributeMaxDynamicSharedMemorySize, SM_STD);
    cudaFuncSetAttribute((const void*)tgemm<64, 256, 256, 3, 1>,   cudaFuncAttributeMaxDynamicSharedMemorySize, SM_STDG);
    cudaFuncSetAttribute((const void*)tgemm<128, 128, 256, 3, 2>,  cudaFuncAttributeMaxDynamicSharedMemorySize, SM_ATTG);
    cudaFuncSetAttribute((const void*)tgemm<64, 256, 1088, 2, 0>,  cudaFuncAttributeMaxDynamicSharedMemorySize, SM_STD);

    // ---- prep ----
    cvt_pad<<<(16384 * 256) / 256, 256>>>(sp, 256, state, 250, 16384);
    cvt_pad<<<(16384 * 576) / 256, 256>>>(xp, 576, x, 576, 16384);

    PrepJobs J;
    auto mk = [](float* dst, const float* W, int Kp, int N0,
                 int b0, int v0, int b1, int v1, int b2, int v2, int NP) {
        PrepJob p; p.dst = dst; p.W = W; p.Kp = Kp; p.N0 = N0;
        p.b0 = b0; p.v0 = v0; p.b1 = b1; p.v1 = v1; p.b2 = b2; p.v2 = v2;
        p.count = NP * Kp; return p;
    };
    J.j[0] = mk(eW,              enc_W,  256, 250, 0, 250, 0, 0, 0, 0, 256);
    J.j[1] = mk(uvW,             core_W, 256, 250, 0, 250, 0, 0, 0, 0, 256);
    J.j[2] = mk(uvW + 256 * 256, core_W, 256, 250, 250, 250, 0, 0, 0, 0, 256);
    J.j[3] = mk(xW,              ctx_W,  256, 250, 0, 250, 0, 0, 0, 0, 256);
    J.j[4] = mk(aW,              att_W1, 256, 100, 0, 250, 0, 0, 0, 0, 128);
    J.j[5] = mk(oW,              out_W,  1088, 250, 0, 250, 250, 250, 500, 576, 256);
    J.cum[0] = 0;
    for (int i = 0; i < 6; i++) J.cum[i + 1] = J.cum[i] + J.j[i].count;
    prep_all<<<(J.cum[6] + 255) / 256, 256>>>(J);

    // 1. enc: s1 = LN(relu(state @ enc_W + b))  [tf32 plane]
    tgemm<64, 256, 256, 0, 1><<<BKTOT / 64, 256, SM_STD>>>(
        sp, nullptr, nullptr, eW,
        enc_b, enc_g, enc_bt, nullptr, nullptr,
        nullptr, nullptr, nullptr, nullptr, nullptr,
        nullptr, s1, 250, 256, 256, 0);
    // 2. UV = s1 @ [W_top ++ W_bot]  (fp32, grid.y = 2)
    tgemm<64, 256, 256, 0, 0><<<dim3(BKTOT / 64, 2), 256, SM_STD>>>(
        s1, nullptr, nullptr, uvW,
        nullptr, nullptr, nullptr, nullptr, nullptr,
        nullptr, nullptr, nullptr, nullptr, nullptr,
        uv, nullptr, 512, 256, 256, 512);
    // 3. LN row stats for the virtual core plane
    ln_stats<<<RR / 8, 256>>>(uv, core_b, mu, rsb);
    // 4. ctx = LN(relu(core @ ctx_W))  [tf32 plane]  — core synthesized in gather
    tgemm<64, 256, 256, 3, 1><<<RR / 64, 256, SM_STDG>>>(
        uv, nullptr, nullptr, xW,
        ctx_b, ctx_g, ctx_bt, nullptr, nullptr,
        mu, rsb, core_b, core_g, core_bt,
        nullptr, cx, 250, 256, 256, 0);
    // 5. att scores — core synthesized in gather
    tgemm<128, 128, 256, 3, 2><<<RR / 128, 256, SM_ATTG>>>(
        uv, nullptr, nullptr, aW,
        att_b1, att_g, att_bt, att_W2, att_b2,
        mu, rsb, core_b, core_g, core_bt,
        att, nullptr, 100, 256, 256, 0);
    // 6. attention-weighted reduction
    effect3<<<BKTOT, 256>>>(cx, att, ef);
    // 7. out: [s1 | eff | x] @ out_W + b
    tgemm<64, 256, 1088, 2, 0><<<BKTOT / 64, 256, SM_STD>>>(
        s1, ef, xp, oW,
        out_b, nullptr, nullptr, nullptr, nullptr,
        nullptr, nullptr, nullptr, nullptr, nullptr,
        out, nullptr, 250, 0, 1088, 250);
}

// round 16
// speedup vs baseline: 1.1197x; 1.0928x over previous
#include <cuda_runtime.h>
#include <cuda_bf16.h>
#include <math.h>
#include <stdint.h>

static constexpr int BKTOT = 16384;
static constexpr int RR    = 114688;

// ---------------- device-global scratch (allocation-free), fp32 tf32-prerounded ----
__device__ __align__(16) float g_sp [16384*256];
__device__ __align__(16) float g_s1 [16384*256];
__device__ __align__(16) float g_uv [16384*512];
__device__ __align__(16) float g_mu [114688];
__device__ __align__(16) float g_rs [114688];
__device__ __align__(16) float g_cx [114688*256];
__device__ __align__(16) float g_att[114688];
__device__ __align__(16) float g_ef [16384*256];
__device__ __align__(16) float g_eW [256*256];
__device__ __align__(16) float g_uvW[512*256];
__device__ __align__(16) float g_xW [256*256];
__device__ __align__(16) float g_aW [128*256];
__device__ __align__(16) float g_oW [256*1088];

// ---------------- helpers ----------------
__device__ __forceinline__ uint32_t smem_u32(const void* p) {
    uint32_t a;
    asm("{ .reg .u64 t; cvta.to.shared.u64 t, %1; cvt.u32.u64 %0, t; }" : "=r"(a) : "l"(p));
    return a;
}
__device__ __forceinline__ void cpa16(uint32_t saddr, const void* g) {
    asm volatile("cp.async.cg.shared.global [%0], [%1], 16;" :: "r"(saddr), "l"(g));
}
#define CP_COMMIT() asm volatile("cp.async.commit_group;" ::: "memory")
#define CP_WAIT(n)  asm volatile("cp.async.wait_group %0;" :: "n"(n) : "memory")

__device__ __forceinline__ float tf32r(float x) {
    uint32_t r;
    asm("cvt.rna.tf32.f32 %0, %1;" : "=r"(r) : "f"(x));
    return __uint_as_float(r);
}
__device__ __forceinline__ void mma_tf32(float* d, const uint32_t* a, const uint32_t* b) {
    asm volatile(
        "mma.sync.aligned.m16n8k8.row.col.f32.tf32.tf32.f32 "
        "{%0,%1,%2,%3}, {%4,%5,%6,%7}, {%8,%9}, {%0,%1,%2,%3};"
        : "+f"(d[0]), "+f"(d[1]), "+f"(d[2]), "+f"(d[3])
        : "r"(a[0]), "r"(a[1]), "r"(a[2]), "r"(a[3]), "r"(b[0]), "r"(b[1]));
}
__device__ __forceinline__ float ftanh(float x) {
    float t = fminf(fmaxf(2.f * x, -30.f), 30.f);
    float e = __expf(t);
    return (e - 1.f) / (e + 1.f);
}
__device__ __forceinline__ float fsigmoid(float z) { return 1.f / (1.f + __expf(-z)); }

// ---------------- prep kernels ----------------
__global__ void cvt_pad(float* __restrict__ dst, int DS,
                        const float* __restrict__ src, int SC, int rows)
{
    int idx = blockIdx.x * blockDim.x + threadIdx.x;
    if (idx >= rows * DS) return;
    int r = idx / DS, c = idx - r * DS;
    float v = (c < SC) ? src[(size_t)r * SC + c] : 0.f;
    dst[idx] = tf32r(v);
}

struct PrepJob {
    float* dst;
    const float* W;
    int Kp, N0;
    int b0, v0, b1, v1, b2, v2;
    int count;
};
struct PrepJobs { PrepJob j[6]; int cum[7]; };

__global__ void prep_all(PrepJobs J)
{
    int e = blockIdx.x * blockDim.x + threadIdx.x;
    if (e >= J.cum[6]) return;
    int ji = 0;
    while (e >= J.cum[ji + 1]) ji++;
    const PrepJob& p = J.j[ji];
    int idx = e - J.cum[ji];
    int n = idx / p.Kp, k = idx - n * p.Kp;
    int piece = (k >= 512) ? 2 : (k >= 256) ? 1 : 0;
    int off = k - ((piece == 2) ? 512 : piece * 256);
    int base  = (piece == 0) ? p.b0 : (piece == 1) ? p.b1 : p.b2;
    int valid = (piece == 0) ? p.v0 : (piece == 1) ? p.v1 : p.v2;
    float v = (off < valid && n < p.N0) ? p.W[(size_t)(base + off) * p.N0 + n] : 0.f;
    p.dst[idx] = tf32r(v);
}

// ---------------- LN row stats, per-b-group smem version ----------------
// One block per b-group: load 8 U + 8 V rows once, warp w computes pairs for i=w.
// Per-pair arithmetic/order identical to the global version -> bitwise-same MU/RS.
__global__ void __launch_bounds__(256) ln_stats_grp(
    const float* __restrict__ UV, const float* __restrict__ bias,
    float* __restrict__ MU, float* __restrict__ RS)
{
    __shared__ float Us[8][256];
    __shared__ float Vs[8][256];
    __shared__ float bs[256];
    const int bg = blockIdx.x;
    const int tid = threadIdx.x;
#pragma unroll
    for (int u = tid; u < 8 * 64; u += 256) {
        int row = u >> 6, c4 = (u & 63) << 2;
        const float* base = UV + (size_t)(bg * 8 + row) * 512;
        *(float4*)&Us[row][c4] = *(const float4*)(base + c4);
        *(float4*)&Vs[row][c4] = *(const float4*)(base + 256 + c4);
    }
    bs[tid] = (tid < 250) ? bias[tid] : 0.f;
    __syncthreads();

    const int w = tid >> 5, lane = tid & 31;
    const int c0 = lane * 8;
#pragma unroll
    for (int p = 0; p < 7; p++) {
        const int i = w, jj = p;
        const int j = jj + (jj >= i ? 1 : 0);
        float s = 0.f, q = 0.f;
#pragma unroll
        for (int h = 0; h < 2; h++) {
            float4 u4 = *(const float4*)&Us[i][c0 + h * 4];
            float4 v4 = *(const float4*)&Vs[j][c0 + h * 4];
            float vv[4] = {u4.x + v4.x, u4.y + v4.y, u4.z + v4.z, u4.w + v4.w};
#pragma unroll
            for (int e = 0; e < 4; e++) {
                int c = c0 + h * 4 + e;
                float xx = (c < 250) ? fmaxf(vv[e] + bs[c], 0.f) : 0.f;
                s += xx; q += xx * xx;
            }
        }
#pragma unroll
        for (int off = 16; off > 0; off >>= 1) {
            s += __shfl_xor_sync(0xffffffffu, s, off);
            q += __shfl_xor_sync(0xffffffffu, q, off);
        }
        float mu = s * (1.f / 250.f);
        float rsv = rsqrtf(q * (1.f / 250.f) - mu * mu + 1e-5f);
        if (lane == 0) {
            int r = bg * 56 + i * 7 + jj;
            MU[r] = mu; RS[r] = rsv;
        }
    }
}

// ---------------- TF32 fused GEMM (2-stage double buffer, BK=32) ----------------
// GATHER: 0 plain (astride); 2 [s1|eff|x(raw, stride 576)]; 3 virtual core from UV
// EPI: 0 bias?+fp32 store; 1 relu+LN -> tf32 plane; 2 tanh+LN+dot(W2)+sigmoid -> scalar
template<int BM, int BN, int KTOT, int GATHER, int EPI>
__global__ void __launch_bounds__(256) tgemm(
    const float* __restrict__ A1, const float* __restrict__ A2, const float* __restrict__ A3,
    const float* __restrict__ Bw,
    const float* __restrict__ bias, const float* __restrict__ gamma, const float* __restrict__ beta,
    const float* __restrict__ W2, const float* __restrict__ b2,
    const float* __restrict__ MU, const float* __restrict__ RS,
    const float* __restrict__ Gb, const float* __restrict__ Gg, const float* __restrict__ Gt,
    float* __restrict__ Cf, float* __restrict__ Cpl,
    int N, int astride, int bstride, int cstride)
{
    constexpr int PADF = 36;
    constexpr int NWM = BM / 32;
    constexpr int NWN = 8 / NWM;
    constexpr int NI  = BN / (8 * NWN);
    constexpr int NST = KTOT / 32;

    extern __shared__ __align__(16) float sm[];
    float* const Asm = sm;
    float* const Bsm = sm + 2 * BM * PADF;
    float* const red0 = sm + 2 * (BM + BN) * PADF;
    float* const red1 = red0 + BM * NWN;
    float* const lnC  = red1 + BM * NWN;   // GATHER==3: [cb|cg|ct] 3*256 floats
    const uint32_t smb = smem_u32(sm);

    const int tid = threadIdx.x, w = tid >> 5, lane = tid & 31;
    const int g = lane >> 2, tq = lane & 3;
    const int wm = w % NWM, wn = w / NWM;
    const int row0 = blockIdx.x * BM;
    const int col0 = blockIdx.y * BN;
    Bw += (size_t)col0 * bstride;

    if (GATHER == 3) {
        if (tid < 256) {
            lnC[tid]       = (tid < 250) ? Gb[tid] : 0.f;
            lnC[256 + tid] = (tid < 250) ? Gg[tid] : 0.f;
            lnC[512 + tid] = (tid < 250) ? Gt[tid] : 0.f;
        }
        __syncthreads();
    }

    float acc[2][NI][4];
#pragma unroll
    for (int mi = 0; mi < 2; mi++)
#pragma unroll
        for (int ni = 0; ni < NI; ni++)
#pragma unroll
            for (int e = 0; e < 4; e++) acc[mi][ni][e] = 0.f;

    auto gatherA = [&](int gr, int k) -> const float* {
        if (GATHER == 0) {
            return A1 + (size_t)gr * astride + k;
        } else {
            if (k < 256) return A1 + (size_t)gr * 256 + k;
            if (k < 512) return A2 + (size_t)gr * 256 + (k - 256);
            return A3 + (size_t)gr * 576 + (k - 512);
        }
    };

    auto loadStage = [&](int t, int st) {
        int kb = t * 32;
        if (GATHER == 3) {
#pragma unroll
            for (int u = tid; u < BM * 8; u += 256) {
                int r = u >> 3, cq = u & 7;
                int gr = row0 + r;
                int k0 = kb + cq * 4;
                int b = gr / 56, rem = gr - b * 56;
                int i = rem / 7, jj = rem - i * 7;
                int j = jj + (jj >= i ? 1 : 0);
                float4 uu = *(const float4*)(A1 + (size_t)(b * 8 + i) * 512 + k0);
                float4 vv = *(const float4*)(A1 + (size_t)(b * 8 + j) * 512 + 256 + k0);
                float m = MU[gr], rsv = RS[gr];
                float4 o;
                {
                    float x0 = fmaxf(uu.x + vv.x + lnC[k0 + 0], 0.f);
                    float x1 = fmaxf(uu.y + vv.y + lnC[k0 + 1], 0.f);
                    float x2 = fmaxf(uu.z + vv.z + lnC[k0 + 2], 0.f);
                    float x3 = fmaxf(uu.w + vv.w + lnC[k0 + 3], 0.f);
                    o.x = tf32r((x0 - m) * rsv * lnC[256 + k0 + 0] + lnC[512 + k0 + 0]);
                    o.y = tf32r((x1 - m) * rsv * lnC[256 + k0 + 1] + lnC[512 + k0 + 1]);
                    o.z = tf32r((x2 - m) * rsv * lnC[256 + k0 + 2] + lnC[512 + k0 + 2]);
                    o.w = tf32r((x3 - m) * rsv * lnC[256 + k0 + 3] + lnC[512 + k0 + 3]);
                }
                *(float4*)&Asm[(st * BM + r) * PADF + cq * 4] = o;
            }
        } else {
#pragma unroll
            for (int u = tid; u < BM * 8; u += 256) {
                int r = u >> 3, cq = u & 7;
                cpa16(smb + (((st * BM + r) * PADF + cq * 4) << 2), gatherA(row0 + r, kb + cq * 4));
            }
        }
#pragma unroll
        for (int u = tid; u < BN * 8; u += 256) {
            int r = u >> 3, cq = u & 7;
            cpa16(smb + ((2 * BM * PADF + (st * BN + r) * PADF + cq * 4) << 2),
                  Bw + (size_t)r * bstride + kb + cq * 4);
        }
    };

    auto compute = [&](int st) {
        const float* At = Asm + st * BM * PADF;
        const float* Bt = Bsm + st * BN * PADF;
#pragma unroll
        for (int kk = 0; kk < 4; kk++) {
            uint32_t a[2][4], b[NI][2];
            const int k = kk * 8 + tq;
#pragma unroll
            for (int mi = 0; mi < 2; mi++) {
                int r = wm * 32 + mi * 16 + g;
                a[mi][0] = __float_as_uint(At[r * PADF + k]);
                a[mi][1] = __float_as_uint(At[(r + 8) * PADF + k]);
                a[mi][2] = __float_as_uint(At[r * PADF + k + 4]);
                a[mi][3] = __float_as_uint(At[(r + 8) * PADF + k + 4]);
            }
#pragma unroll
            for (int ni = 0; ni < NI; ni++) {
                int r = wn * (NI * 8) + ni * 8 + g;
                b[ni][0] = __float_as_uint(Bt[r * PADF + k]);
                b[ni][1] = __float_as_uint(Bt[r * PADF + k + 4]);
            }
#pragma unroll
            for (int mi = 0; mi < 2; mi++)
#pragma unroll
                for (int ni = 0; ni < NI; ni++)
                    mma_tf32(acc[mi][ni], a[mi], b[ni]);
        }
    };

    loadStage(0, 0); CP_COMMIT();
    for (int t = 0; t < NST; t++) {
        if (t + 1 < NST) { loadStage(t + 1, (t + 1) & 1); CP_COMMIT(); CP_WAIT(1); }
        else             { CP_WAIT(0); }
        __syncthreads();
        compute(t & 1);
        __syncthreads();
    }

    // ---------------- epilogues ----------------
    if (EPI == 0) {
#pragma unroll
        for (int mi = 0; mi < 2; mi++) {
            int r0 = row0 + wm * 32 + mi * 16 + g;
#pragma unroll
            for (int ni = 0; ni < NI; ni++) {
                int gc0 = col0 + wn * (NI * 8) + ni * 8 + tq * 2, gc1 = gc0 + 1;
                if (gc0 < N) {
                    float bv = bias ? bias[gc0] : 0.f;
                    Cf[(size_t)r0 * cstride + gc0]       = acc[mi][ni][0] + bv;
                    Cf[(size_t)(r0 + 8) * cstride + gc0] = acc[mi][ni][2] + bv;
                }
                if (gc1 < N) {
                    float bv = bias ? bias[gc1] : 0.f;
                    Cf[(size_t)r0 * cstride + gc1]       = acc[mi][ni][1] + bv;
                    Cf[(size_t)(r0 + 8) * cstride + gc1] = acc[mi][ni][3] + bv;
                }
            }
        }
        return;
    }

    // stat phase (EPI 1/2)
    float s[2][2] = {{0,0},{0,0}}, q[2][2] = {{0,0},{0,0}};
#pragma unroll
    for (int mi = 0; mi < 2; mi++)
#pragma unroll
        for (int ni = 0; ni < NI; ni++) {
            int c0 = wn * (NI * 8) + ni * 8 + tq * 2, c1 = c0 + 1;
            float b0v = (c0 < N) ? bias[c0] : 0.f;
            float b1v = (c1 < N) ? bias[c1] : 0.f;
            float v0 = acc[mi][ni][0] + b0v, v1 = acc[mi][ni][1] + b1v;
            float v2 = acc[mi][ni][2] + b0v, v3 = acc[mi][ni][3] + b1v;
            if (EPI == 2) {
                v0 = ftanh(v0); v1 = ftanh(v1); v2 = ftanh(v2); v3 = ftanh(v3);
            } else {
                v0 = fmaxf(v0, 0.f); v1 = fmaxf(v1, 0.f);
                v2 = fmaxf(v2, 0.f); v3 = fmaxf(v3, 0.f);
            }
            if (c0 >= N) { v0 = 0.f; v2 = 0.f; }
            if (c1 >= N) { v1 = 0.f; v3 = 0.f; }
            acc[mi][ni][0] = v0; acc[mi][ni][1] = v1;
            acc[mi][ni][2] = v2; acc[mi][ni][3] = v3;
            s[mi][0] += v0 + v1; q[mi][0] += v0 * v0 + v1 * v1;
            s[mi][1] += v2 + v3; q[mi][1] += v2 * v2 + v3 * v3;
        }
#pragma unroll
    for (int off = 1; off <= 2; off <<= 1)
#pragma unroll
        for (int mi = 0; mi < 2; mi++)
#pragma unroll
            for (int dr = 0; dr < 2; dr++) {
                s[mi][dr] += __shfl_xor_sync(0xffffffffu, s[mi][dr], off);
                q[mi][dr] += __shfl_xor_sync(0xffffffffu, q[mi][dr], off);
            }
    if (tq == 0)
#pragma unroll
        for (int mi = 0; mi < 2; mi++)
#pragma unroll
            for (int dr = 0; dr < 2; dr++) {
                int r = wm * 32 + mi * 16 + g + 8 * dr;
                red0[r * NWN + wn] = s[mi][dr];
                red1[r * NWN + wn] = q[mi][dr];
            }
    __syncthreads();
    float mu[2][2], rs[2][2];
    const float invN = 1.f / (float)N;
#pragma unroll
    for (int mi = 0; mi < 2; mi++)
#pragma unroll
        for (int dr = 0; dr < 2; dr++) {
            int r = wm * 32 + mi * 16 + g + 8 * dr;
            float ss = 0.f, qq = 0.f;
#pragma unroll
            for (int xx = 0; xx < NWN; xx++) { ss += red0[r * NWN + xx]; qq += red1[r * NWN + xx]; }
            mu[mi][dr] = ss * invN;
            rs[mi][dr] = rsqrtf(qq * invN - mu[mi][dr] * mu[mi][dr] + 1e-5f);
        }

    if (EPI == 1) {
#pragma unroll
        for (int mi = 0; mi < 2; mi++) {
            int gr0 = row0 + wm * 32 + mi * 16 + g;
#pragma unroll
            for (int ni = 0; ni < NI; ni++) {
                int c0 = wn * (NI * 8) + ni * 8 + tq * 2, c1 = c0 + 1;
                float g0 = (c0 < N) ? gamma[c0] : 0.f, g1 = (c1 < N) ? gamma[c1] : 0.f;
                float t0 = (c0 < N) ? beta[c0] : 0.f,  t1 = (c1 < N) ? beta[c1]  : 0.f;
#pragma unroll
                for (int dr = 0; dr < 2; dr++) {
                    int gr = gr0 + 8 * dr;
                    float w0 = (c0 < N) ? (acc[mi][ni][2*dr+0] - mu[mi][dr]) * rs[mi][dr] * g0 + t0 : 0.f;
                    float w1 = (c1 < N) ? (acc[mi][ni][2*dr+1] - mu[mi][dr]) * rs[mi][dr] * g1 + t1 : 0.f;
                    float2 wv = make_float2(tf32r(w0), tf32r(w1));
                    *(float2*)(Cpl + (size_t)gr * 256 + c0) = wv;
                }
            }
        }
        return;
    }

    // EPI == 2
    {
        float d[2][2] = {{0,0},{0,0}};
#pragma unroll
        for (int mi = 0; mi < 2; mi++)
#pragma unroll
            for (int ni = 0; ni < NI; ni++) {
                int c0 = wn * (NI * 8) + ni * 8 + tq * 2, c1 = c0 + 1;
#pragma unroll
                for (int dr = 0; dr < 2; dr++) {
                    if (c0 < N)
                        d[mi][dr] += ((acc[mi][ni][2*dr+0] - mu[mi][dr]) * rs[mi][dr] * gamma[c0] + beta[c0]) * W2[c0];
                    if (c1 < N)
                        d[mi][dr] += ((acc[mi][ni][2*dr+1] - mu[mi][dr]) * rs[mi][dr] * gamma[c1] + beta[c1]) * W2[c1];
                }
            }
#pragma unroll
        for (int off = 1; off <= 2; off <<= 1)
#pragma unroll
            for (int mi = 0; mi < 2; mi++)
#pragma unroll
                for (int dr = 0; dr < 2; dr++)
                    d[mi][dr] += __shfl_xor_sync(0xffffffffu, d[mi][dr], off);
        __syncthreads();
        if (tq == 0)
#pragma unroll
            for (int mi = 0; mi < 2; mi++)
#pragma unroll
                for (int dr = 0; dr < 2; dr++) {
                    int r = wm * 32 + mi * 16 + g + 8 * dr;
                    red0[r * NWN + wn] = d[mi][dr];
                }
        __syncthreads();
        if (wn == 0 && tq == 0) {
            float bb = b2[0];
#pragma unroll
            for (int mi = 0; mi < 2; mi++)
#pragma unroll
                for (int dr = 0; dr < 2; dr++) {
                    int r = wm * 32 + mi * 16 + g + 8 * dr;
                    float dd = 0.f;
#pragma unroll
                    for (int xx = 0; xx < NWN; xx++) dd += red0[r * NWN + xx];
                    Cf[row0 + r] = fsigmoid(dd + bb);
                }
        }
    }
}

// effect: eff[bk][c] = sum_j ctx[bk*7+j][c] * att[bk*7+j], tf32-rounded
__global__ void effect3(const float* __restrict__ cx, const float* __restrict__ att,
                        float* __restrict__ eff)
{
    int bk = blockIdx.x, c = threadIdx.x;
    __shared__ float a[7];
    if (c < 7) a[c] = att[bk * 7 + c];
    __syncthreads();
    size_t base = (size_t)bk * 7 * 256 + c;
    float s = 0.f;
#pragma unroll
    for (int j = 0; j < 7; j++) s = fmaf(cx[base + j * 256], a[j], s);
    eff[(size_t)bk * 256 + c] = tf32r(s);
}

extern "C" void kernel_launch(void* const* d_in, const int* in_sizes, int n_in,
                              void* d_out, int out_size)
{
    const float* x       = (const float*)d_in[0];
    const float* state   = (const float*)d_in[1];
    const float* enc_W   = (const float*)d_in[2];
    const float* enc_b   = (const float*)d_in[3];
    const float* enc_g   = (const float*)d_in[4];
    const float* enc_bt  = (const float*)d_in[5];
    const float* core_W  = (const float*)d_in[6];
    const float* core_b  = (const float*)d_in[7];
    const float* core_g  = (const float*)d_in[8];
    const float* core_bt = (const float*)d_in[9];
    const float* ctx_W   = (const float*)d_in[10];
    const float* ctx_b   = (const float*)d_in[11];
    const float* ctx_g   = (const float*)d_in[12];
    const float* ctx_bt  = (const float*)d_in[13];
    const float* att_W1  = (const float*)d_in[14];
    const float* att_b1  = (const float*)d_in[15];
    const float* att_g   = (const float*)d_in[16];
    const float* att_bt  = (const float*)d_in[17];
    const float* att_W2  = (const float*)d_in[18];
    const float* att_b2  = (const float*)d_in[19];
    const float* out_W   = (const float*)d_in[20];
    const float* out_b   = (const float*)d_in[21];
    float* out = (float*)d_out;

    float *sp, *s1, *uv, *mu, *rsb, *cx, *att, *ef, *eW, *uvW, *xW, *aW, *oW;
    cudaGetSymbolAddress((void**)&sp, g_sp);
    cudaGetSymbolAddress((void**)&s1, g_s1);   cudaGetSymbolAddress((void**)&uv, g_uv);
    cudaGetSymbolAddress((void**)&mu, g_mu);   cudaGetSymbolAddress((void**)&rsb, g_rs);
    cudaGetSymbolAddress((void**)&cx, g_cx);   cudaGetSymbolAddress((void**)&att, g_att);
    cudaGetSymbolAddress((void**)&ef, g_ef);   cudaGetSymbolAddress((void**)&eW, g_eW);
    cudaGetSymbolAddress((void**)&uvW, g_uvW); cudaGetSymbolAddress((void**)&xW, g_xW);
    cudaGetSymbolAddress((void**)&aW, g_aW);   cudaGetSymbolAddress((void**)&oW, g_oW);

    const int SM_STD  = 2 * (64 + 256) * 36 * 4 + 2 * 64 * 4 * 4;              // 94208
    const int SM_STDG = SM_STD + 768 * 4;                                      // 97280
    const int SM_ATT  = 2 * (128 + 128) * 36 * 4 + 2 * 128 * 2 * 4;            // 75776
    const int SM_ATTG = SM_ATT + 768 * 4;                                      // 78848
    cudaFuncSetAttribute((const void*)tgemm<64, 256, 256, 0, 1>,   cudaFuncAttributeMaxDynamicSharedMemorySize, SM_STD);
    cudaFuncSetAttribute((const void*)tgemm<64, 256, 256, 0, 0>,   cudaFuncAttributeMaxDynamicSharedMemorySize, SM_STD);
    cudaFuncSetAttribute((const void*)tgemm<64, 256, 256, 3, 1>,   cudaFuncAttributeMaxDynamicSharedMemorySize, SM_STDG);
    cudaFuncSetAttribute((const void*)tgemm<128, 128, 256, 3, 2>,  cudaFuncAttributeMaxDynamicSharedMemorySize, SM_ATTG);
    cudaFuncSetAttribute((const void*)tgemm<64, 256, 1088, 2, 0>,  cudaFuncAttributeMaxDynamicSharedMemorySize, SM_STD);

    // ---- prep ----
    cvt_pad<<<(16384 * 256) / 256, 256>>>(sp, 256, state, 250, 16384);

    PrepJobs J;
    auto mk = [](float* dst, const float* W, int Kp, int N0,
                 int b0, int v0, int b1, int v1, int b2, int v2, int NP) {
        PrepJob p; p.dst = dst; p.W = W; p.Kp = Kp; p.N0 = N0;
        p.b0 = b0; p.v0 = v0; p.b1 = b1; p.v1 = v1; p.b2 = b2; p.v2 = v2;
        p.count = NP * Kp; return p;
    };
    J.j[0] = mk(eW,              enc_W,  256, 250, 0, 250, 0, 0, 0, 0, 256);
    J.j[1] = mk(uvW,             core_W, 256, 250, 0, 250, 0, 0, 0, 0, 256);
    J.j[2] = mk(uvW + 256 * 256, core_W, 256, 250, 250, 250, 0, 0, 0, 0, 256);
    J.j[3] = mk(xW,              ctx_W,  256, 250, 0, 250, 0, 0, 0, 0, 256);
    J.j[4] = mk(aW,              att_W1, 256, 100, 0, 250, 0, 0, 0, 0, 128);
    J.j[5] = mk(oW,              out_W,  1088, 250, 0, 250, 250, 250, 500, 576, 256);
    J.cum[0] = 0;
    for (int i = 0; i < 6; i++) J.cum[i + 1] = J.cum[i] + J.j[i].count;
    prep_all<<<(J.cum[6] + 255) / 256, 256>>>(J);

    // 1. enc: s1 = LN(relu(state @ enc_W + b))  [tf32 plane]
    tgemm<64, 256, 256, 0, 1><<<BKTOT / 64, 256, SM_STD>>>(
        sp, nullptr, nullptr, eW,
        enc_b, enc_g, enc_bt, nullptr, nullptr,
        nullptr, nullptr, nullptr, nullptr, nullptr,
        nullptr, s1, 250, 256, 256, 0);
    // 2. UV = s1 @ [W_top ++ W_bot]  (fp32, grid.y = 2)
    tgemm<64, 256, 256, 0, 0><<<dim3(BKTOT / 64, 2), 256, SM_STD>>>(
        s1, nullptr, nullptr, uvW,
        nullptr, nullptr, nullptr, nullptr, nullptr,
        nullptr, nullptr, nullptr, nullptr, nullptr,
        uv, nullptr, 512, 256, 256, 512);
    // 3. LN row stats (smem b-group version, bitwise-identical output)
    ln_stats_grp<<<BKTOT / 8, 256>>>(uv, core_b, mu, rsb);
    // 4. ctx = LN(relu(core @ ctx_W))  [tf32 plane]  — core synthesized in gather
    tgemm<64, 256, 256, 3, 1><<<RR / 64, 256, SM_STDG>>>(
        uv, nullptr, nullptr, xW,
        ctx_b, ctx_g, ctx_bt, nullptr, nullptr,
        mu, rsb, core_b, core_g, core_bt,
        nullptr, cx, 250, 256, 256, 0);
    // 5. att scores — core synthesized in gather
    tgemm<128, 128, 256, 3, 2><<<RR / 128, 256, SM_ATTG>>>(
        uv, nullptr, nullptr, aW,
        att_b1, att_g, att_bt, att_W2, att_b2,
        mu, rsb, core_b, core_g, core_bt,
        att, nullptr, 100, 256, 256, 0);
    // 6. attention-weighted reduction
    effect3<<<BKTOT, 256>>>(cx, att, ef);
    // 7. out: [s1 | eff | x(raw)] @ out_W + b
    tgemm<64, 256, 1088, 2, 0><<<BKTOT / 64, 256, SM_STD>>>(
        s1, ef, x, oW,
        out_b, nullptr, nullptr, nullptr, nullptr,
        nullptr, nullptr, nullptr, nullptr, nullptr,
        out, nullptr, 250, 0, 1088, 250);
}